// round 12
// baseline (speedup 1.0000x reference)
#include <cuda_runtime.h>

#define BB 256
#define TT 1024
#define DD 128
#define LL 16
#define OO 256

// ---- recurrence geometry (R7/R11 tiling — best measured): 256 thr = 8 warps =
// 4 k-chunks x 2 o-halves; thread: 64 k x 4 o; 48 k in regs, 16 k via smem.
#define NTHR 256
#define RSM_TSTRIDE 272     // 32 u64 data + 2 u64 pad per thread

#define PART_OFF 0          // partial[4 chunk][2 batch][256 o] f32 = 8 KB
#define S_OFF    8192       // state [2 buf][2 batch][256] f32     = 4 KB
#define RSM_OFF  12288      // Rsm: 256 * 272 = 69632 B
#define SMEM_BYTES (RSM_OFF + NTHR * RSM_TSTRIDE)   // 81920 B

// +OO pad: lets recur prefetch agg[t+1] unconditionally at t = TT-1.
__device__ float g_agg[(size_t)BB * TT * OO + OO];

#define FMA2(acc, a, b) asm("fma.rn.f32x2 %0, %1, %2, %0;" : "+l"(acc) : "l"(a), "l"(b))

__device__ __forceinline__ void lds_v2u64(unsigned long long& a, unsigned long long& b,
                                          unsigned int addr) {
    asm volatile("ld.shared.v2.u64 {%0, %1}, [%2];" : "=l"(a), "=l"(b) : "r"(addr));
}
__device__ __forceinline__ float lds_f32(unsigned int addr) {
    float v; asm volatile("ld.shared.f32 %0, [%1];" : "=f"(v) : "r"(addr)); return v;
}
__device__ __forceinline__ void sts_f32(unsigned int addr, float v) {
    asm volatile("st.shared.f32 [%0], %1;" :: "r"(addr), "f"(v));
}
__device__ __forceinline__ void sts_u64(unsigned int addr, unsigned long long v) {
    asm volatile("st.shared.u64 [%0], %1;" :: "r"(addr), "l"(v));
}

// ---------------------------------------------------------------------------
// Kernel 1: agg[b,t,o] = sum_l act_l( x[b,t,:]·sub_W[l,:] + sub_b[l] ) * agg_W[l,o]
// 64 rows per CTA. pre-dot packed f32x2 over D; agg matmul now ALSO packed:
// l-dimension processed in pairs via f32x2 — act pair (l,l+1) is one broadcast
// LDS.64, weights pre-packed (w_l, w_{l+1}) in 32 u64 regs. Halves matmul FMA
// pipe work vs R11's scalar FFMA (which measured at the scalar roofline).
// ---------------------------------------------------------------------------
__global__ void __launch_bounds__(256) act_agg_kernel(
    const float* __restrict__ x, const float* __restrict__ subW,
    const float* __restrict__ subb, const float* __restrict__ aggW)
{
    __shared__ float xs[64][DD];          // 32 KB  (row = 512 B, 16B-aligned)
    __shared__ float ws[LL][DD + 4];      // 8.25 KB (row stride 528 B, 16B-aligned)
    __shared__ float as_[64][LL + 2];     // rows 72 B -> 8B-aligned for LDS.64

    const int tid = threadIdx.x;
    const size_t row0 = (size_t)blockIdx.x * 64;

    for (int i = tid; i < LL * DD; i += 256) ws[i / DD][i % DD] = subW[i];
    {
        const float4* xg = (const float4*)(x + row0 * DD);
        float4* xs4 = (float4*)&xs[0][0];
#pragma unroll
        for (int i = 0; i < 8; i++) xs4[tid + 256 * i] = xg[tid + 256 * i];
    }
    __syncthreads();

    // ---- pre + activation: tasks (r, l), 4 rows per thread, f32x2 dot over D
    {
        const int l = tid & 15;
        const int rb = tid >> 4;
        const float bias = subb[l];
        const ulonglong2* wr = (const ulonglong2*)&ws[l][0];   // 32 x (2 f32x2) = 128 floats
#pragma unroll
        for (int it = 0; it < 4; it++) {
            const int r = rb + 16 * it;
            const ulonglong2* xr = (const ulonglong2*)&xs[r][0];
            unsigned long long acc = 0ULL;                      // (0.f, 0.f)
#pragma unroll
            for (int i = 0; i < 32; i++) {   // 32 iters x 4 floats = D=128 (full row)
                ulonglong2 a = xr[i], b = wr[i];
                FMA2(acc, a.x, b.x);
                FMA2(acc, a.y, b.y);
            }
            float lo, hi;
            asm("mov.b64 {%0, %1}, %2;" : "=f"(lo), "=f"(hi) : "l"(acc));
            const float s = lo + hi + bias;
            float v;
            const int m = l & 3;
            if (m == 0)      v = tanhf(s);
            else if (m == 1) v = fmaxf(s, 0.f);
            else if (m == 2) v = 1.f / (1.f + expf(-s));
            else             v = s;
            as_[r][l] = v;
        }
    }
    __syncthreads();

    // ---- aggregation: thread = (o-quad, 16-row group); l packed in pairs.
    // acc u64 lanes hold (even-l sum, odd-l sum); folded at store.
    {
        const int oq = tid & 63;          // o columns 4*oq .. 4*oq+3
        const int rq = tid >> 6;          // rows 16*rq .. 16*rq+15
        const int o0 = oq * 4;

        // weights packed (aggW[2p][o], aggW[2p+1][o]) : 8 pairs x 4 cols
        unsigned long long wp[8][4];
#pragma unroll
        for (int p = 0; p < 8; p++)
#pragma unroll
            for (int j = 0; j < 4; j++) {
                float lo = aggW[(2 * p) * OO + o0 + j];
                float hi = aggW[(2 * p + 1) * OO + o0 + j];
                asm("mov.b64 %0, {%1, %2};" : "=l"(wp[p][j]) : "f"(lo), "f"(hi));
            }

        float* outp = g_agg + (row0 + rq * 16) * (size_t)OO + o0;
#pragma unroll
        for (int rr = 0; rr < 16; rr++) {
            const int r = rq * 16 + rr;
            const unsigned long long* ar = (const unsigned long long*)&as_[r][0];
            unsigned long long acc0 = 0, acc1 = 0, acc2 = 0, acc3 = 0;
#pragma unroll
            for (int p = 0; p < 8; p++) {
                const unsigned long long av = ar[p];   // broadcast LDS.64: (act_2p, act_2p+1)
                FMA2(acc0, av, wp[p][0]);
                FMA2(acc1, av, wp[p][1]);
                FMA2(acc2, av, wp[p][2]);
                FMA2(acc3, av, wp[p][3]);
            }
            float4 o4;
            float lo, hi;
            asm("mov.b64 {%0,%1}, %2;" : "=f"(lo), "=f"(hi) : "l"(acc0)); o4.x = lo + hi;
            asm("mov.b64 {%0,%1}, %2;" : "=f"(lo), "=f"(hi) : "l"(acc1)); o4.y = lo + hi;
            asm("mov.b64 {%0,%1}, %2;" : "=f"(lo), "=f"(hi) : "l"(acc2)); o4.z = lo + hi;
            asm("mov.b64 {%0,%1}, %2;" : "=f"(lo), "=f"(hi) : "l"(acc3)); o4.w = lo + hi;
            *(float4*)(outp + (size_t)rr * OO) = o4;    // coalesced STG.128
        }
    }
}

// ---------------------------------------------------------------------------
// Kernel 2: recurrence s_t = agg_t + s_{t-1} @ R — R11 VERBATIM (980.9 us
// measured; protected — do not touch).
// ---------------------------------------------------------------------------
__global__ void __launch_bounds__(NTHR, 1) recur_kernel(const float* __restrict__ R,
                                                        float* __restrict__ out)
{
    extern __shared__ unsigned char dyn[];
    unsigned int sm;
    asm("{ .reg .u64 t0; cvta.to.shared.u64 t0, %1; cvt.u32.u64 %0, t0; }"
        : "=r"(sm) : "l"(dyn));

    const int tid  = threadIdx.x;
    const int lane = tid & 31;
    const int w    = tid >> 5;
    const int c    = w & 3;        // k-chunk: rows 64c .. 64c+63
    const int h    = w >> 2;       // o-half
    const int b0   = blockIdx.x * 2;

    // ---- 24 k-pairs (48 rows) x 4 o-cols into registers
    unsigned long long Rp[24 * 4];
#pragma unroll
    for (int i = 0; i < 24; i++)
#pragma unroll
        for (int j = 0; j < 4; j++) {
            const int k = c * 64 + 2 * i;
            const int o = h * 128 + lane + 32 * j;
            float lo = R[(size_t)k * OO + o];
            float hi = R[(size_t)(k + 1) * OO + o];
            asm("mov.b64 %0, {%1, %2};" : "=l"(Rp[i * 4 + j]) : "f"(lo), "f"(hi));
        }

    // ---- 8 k-pairs (16 rows) x 4 o-cols into per-thread smem rows
    const unsigned int rsm = sm + RSM_OFF + tid * RSM_TSTRIDE;
#pragma unroll
    for (int i = 0; i < 8; i++)
#pragma unroll
        for (int j = 0; j < 4; j++) {
            const int k = c * 64 + 48 + 2 * i;
            const int o = h * 128 + lane + 32 * j;
            float lo = R[(size_t)k * OO + o];
            float hi = R[(size_t)(k + 1) * OO + o];
            unsigned long long p;
            asm("mov.b64 %0, {%1, %2};" : "=l"(p) : "f"(lo), "f"(hi));
            sts_u64(rsm + (unsigned)(i * 4 + j) * 8, p);
        }

    // zero initial state in buffer 0 (2 batches x 256)
    sts_f32(sm + S_OFF + 0 * 1024 + tid * 4, 0.f);
    sts_f32(sm + S_OFF + 1 * 1024 + tid * 4, 0.f);

    // phase-2 identity: thread -> output column o = tid, both batches
    const float* aggp0 = g_agg + ((size_t)b0       * TT) * OO + tid;
    const float* aggp1 = g_agg + ((size_t)(b0 + 1) * TT) * OO + tid;
    float*       outp0 = out   + ((size_t)b0       * TT) * OO + tid;
    float*       outp1 = out   + ((size_t)(b0 + 1) * TT) * OO + tid;
    float a0 = __ldg(aggp0), a1 = __ldg(aggp1);

    // addresses
    const unsigned int schunk = sm + S_OFF + c * 256;
    const unsigned int pw     = sm + PART_OFF + c * 2048 + (h * 128 + lane) * 4;
    const unsigned int pr     = sm + PART_OFF + tid * 4;
    const unsigned int sw     = sm + S_OFF + tid * 4;

    __syncthreads();

    for (int t = 0; t < TT; t++) {
        const int p = t & 1;
        // branchless prefetch of agg[t+1] (g_agg padded by one row)
        const float a0n = __ldg(aggp0 + (size_t)(t + 1) * OO);
        const float a1n = __ldg(aggp1 + (size_t)(t + 1) * OO);

        const unsigned int sA = schunk + p * 2048;
        const unsigned int sB = sA + 1024;

        unsigned long long acc0 = 0, acc1 = 0, acc2 = 0, acc3 = 0,
                           acc4 = 0, acc5 = 0, acc6 = 0, acc7 = 0;

        // -------- phase 1a: 24 register k-pairs --------
#pragma unroll
        for (int ii = 0; ii < 12; ii++) {
            unsigned long long ax, ay, bx, by;
            lds_v2u64(ax, ay, sA + ii * 16);
            lds_v2u64(bx, by, sB + ii * 16);
            FMA2(acc0, ax, Rp[(2*ii)*4+0]);   FMA2(acc4, bx, Rp[(2*ii)*4+0]);
            FMA2(acc1, ax, Rp[(2*ii)*4+1]);   FMA2(acc5, bx, Rp[(2*ii)*4+1]);
            FMA2(acc2, ax, Rp[(2*ii)*4+2]);   FMA2(acc6, bx, Rp[(2*ii)*4+2]);
            FMA2(acc3, ax, Rp[(2*ii)*4+3]);   FMA2(acc7, bx, Rp[(2*ii)*4+3]);
            FMA2(acc0, ay, Rp[(2*ii+1)*4+0]); FMA2(acc4, by, Rp[(2*ii+1)*4+0]);
            FMA2(acc1, ay, Rp[(2*ii+1)*4+1]); FMA2(acc5, by, Rp[(2*ii+1)*4+1]);
            FMA2(acc2, ay, Rp[(2*ii+1)*4+2]); FMA2(acc6, by, Rp[(2*ii+1)*4+2]);
            FMA2(acc3, ay, Rp[(2*ii+1)*4+3]); FMA2(acc7, by, Rp[(2*ii+1)*4+3]);
        }
        // -------- phase 1b: 8 smem k-pairs --------
#pragma unroll
        for (int q = 0; q < 4; q++) {
            unsigned long long ax, ay, bx, by;
            lds_v2u64(ax, ay, sA + (12 + q) * 16);
            lds_v2u64(bx, by, sB + (12 + q) * 16);
            unsigned long long r0, r1, r2, r3;
            lds_v2u64(r0, r1, rsm + (2*q) * 32);
            lds_v2u64(r2, r3, rsm + (2*q) * 32 + 16);
            FMA2(acc0, ax, r0); FMA2(acc4, bx, r0);
            FMA2(acc1, ax, r1); FMA2(acc5, bx, r1);
            FMA2(acc2, ax, r2); FMA2(acc6, bx, r2);
            FMA2(acc3, ax, r3); FMA2(acc7, bx, r3);
            lds_v2u64(r0, r1, rsm + (2*q+1) * 32);
            lds_v2u64(r2, r3, rsm + (2*q+1) * 32 + 16);
            FMA2(acc0, ay, r0); FMA2(acc4, by, r0);
            FMA2(acc1, ay, r1); FMA2(acc5, by, r1);
            FMA2(acc2, ay, r2); FMA2(acc6, by, r2);
            FMA2(acc3, ay, r3); FMA2(acc7, by, r3);
        }

        // combine even/odd-k halves, store 8 partials (coalesced STS.32)
        {
            float x, y;
            asm("mov.b64 {%0,%1}, %2;" : "=f"(x), "=f"(y) : "l"(acc0)); sts_f32(pw + 0*1024 + 0*128, x + y);
            asm("mov.b64 {%0,%1}, %2;" : "=f"(x), "=f"(y) : "l"(acc1)); sts_f32(pw + 0*1024 + 1*128, x + y);
            asm("mov.b64 {%0,%1}, %2;" : "=f"(x), "=f"(y) : "l"(acc2)); sts_f32(pw + 0*1024 + 2*128, x + y);
            asm("mov.b64 {%0,%1}, %2;" : "=f"(x), "=f"(y) : "l"(acc3)); sts_f32(pw + 0*1024 + 3*128, x + y);
            asm("mov.b64 {%0,%1}, %2;" : "=f"(x), "=f"(y) : "l"(acc4)); sts_f32(pw + 1*1024 + 0*128, x + y);
            asm("mov.b64 {%0,%1}, %2;" : "=f"(x), "=f"(y) : "l"(acc5)); sts_f32(pw + 1*1024 + 1*128, x + y);
            asm("mov.b64 {%0,%1}, %2;" : "=f"(x), "=f"(y) : "l"(acc6)); sts_f32(pw + 1*1024 + 2*128, x + y);
            asm("mov.b64 {%0,%1}, %2;" : "=f"(x), "=f"(y) : "l"(acc7)); sts_f32(pw + 1*1024 + 3*128, x + y);
        }
        __syncthreads();

        // -------- phase 2: reduce 4 chunk-partials per (o,batch), publish --------
        float r0 = a0 + lds_f32(pr + 0*2048)
                      + lds_f32(pr + 1*2048)
                      + lds_f32(pr + 2*2048)
                      + lds_f32(pr + 3*2048);
        float r1 = a1 + lds_f32(pr + 0*2048 + 1024)
                      + lds_f32(pr + 1*2048 + 1024)
                      + lds_f32(pr + 2*2048 + 1024)
                      + lds_f32(pr + 3*2048 + 1024);
        const unsigned int swp = sw + (p ^ 1) * 2048;
        sts_f32(swp, r0);
        sts_f32(swp + 1024, r1);
        *outp0 = r0;
        *outp1 = r1;
        outp0 += OO;
        outp1 += OO;

        a0 = a0n; a1 = a1n;
        __syncthreads();
    }
}

// ---------------------------------------------------------------------------
extern "C" void kernel_launch(void* const* d_in, const int* in_sizes, int n_in,
                              void* d_out, int out_size)
{
    const float* x    = (const float*)d_in[0];
    const float* subW = (const float*)d_in[1];
    const float* subb = (const float*)d_in[2];
    const float* aggW = (const float*)d_in[3];
    const float* R    = (const float*)d_in[4];
    float* out = (float*)d_out;

    cudaFuncSetAttribute(recur_kernel, cudaFuncAttributeMaxDynamicSharedMemorySize,
                         SMEM_BYTES);

    act_agg_kernel<<<(BB * TT) / 64, 256>>>(x, subW, subb, aggW);
    recur_kernel<<<BB / 2, NTHR, SMEM_BYTES>>>(R, out);
}